// round 17
// baseline (speedup 1.0000x reference)
#include <cuda_runtime.h>
#include <cuda_fp16.h>
#include <cstdint>

// ---------------- problem constants ----------------
#define NB      32
#define DIM     64
#define HW      1024
#define KCODES  2048
#define TOK_TILE 128
#define NPAIRS   256          // token tiles
#define NBLOCKS  512          // 2 blocks per token tile (code halves)
#define NTHREADS 256
#define NWARPS   8
#define HTILES   8            // 128-code tiles per half
#define WLIST    512          // per-warp candidate capacity

// int8 screening constants: s = 5.5/127 global scale
#define QINV     23.0909090909f        // 127/5.5
#define INV2S2   266.628099f           // 1/(2*s*s)
#define M_INT    480                   // margin = 1.8 (v-space) / (2 s^2)

// ---------------- dynamic smem layout (bytes) ----------------
#define A_STRIDE 132
#define A_OFF    0u                       // fp32 A [64][132]  (33792 B)
#define B_OFF    33792u                   // 2 buffers x 8KB packed s8 tiles
#define B_BUF    8192u
#define CN_OFF   50176u                   // 2 x 128 ints (packed -cn/(2s^2))
#define DW_OFF   51200u                   // 192 floats
#define DB_OFF   51968u                   // 4 floats
#define CNT_OFF  51984u                   // 8 u32 per-warp counters (+pad)
#define LIST_OFF 52032u                   // 8 x WLIST u32 (16384 B)
#define RED_OFF  68416u                   // 2 x 256 floats
#define SMEM_TOTAL 70464u

__device__ float g_cnorm[KCODES];         // exact ||e||^2 (refine path)
// packed int accumulator inits: per 128-code tile 128 ints, [ntp 8][tig 4] int4
__device__ int g_cni[16 * 128];
__device__ float g_partial[2 * NPAIRS];
__device__ unsigned int g_done = 0;
__device__ unsigned int g_pair[NPAIRS];
__device__ unsigned long long g_tokmin[NPAIRS * TOK_TILE];
// packed s8 codebook: per 128-code tile 2048 u32 = [nt 16][lane 32] uint4
__device__ uint32_t g_cbq[16 * 2048];

// ---------------- helpers ----------------
__device__ __forceinline__ uint32_t smem_u32(const void* p) {
    uint32_t a;
    asm("{ .reg .u64 t; cvta.to.shared.u64 t, %1; cvt.u32.u64 %0, t; }" : "=r"(a) : "l"(p));
    return a;
}
__device__ __forceinline__ int q8(float x) {
    int q = __float2int_rn(x * QINV);
    return max(-127, min(127, q));
}
__device__ __forceinline__ uint32_t pack4(float a, float b, float c, float d) {
    return (uint32_t)(q8(a) & 255) | ((uint32_t)(q8(b) & 255) << 8)
         | ((uint32_t)(q8(c) & 255) << 16) | ((uint32_t)(q8(d) & 255) << 24);
}
__device__ __forceinline__ void mma_s8(int* d, const uint32_t* a,
                                       uint32_t b0, uint32_t b1) {
    asm volatile(
        "mma.sync.aligned.m16n8k32.row.col.s32.s8.s8.s32 "
        "{%0,%1,%2,%3}, {%4,%5,%6,%7}, {%8,%9}, {%0,%1,%2,%3};"
        : "+r"(d[0]), "+r"(d[1]), "+r"(d[2]), "+r"(d[3])
        : "r"(a[0]), "r"(a[1]), "r"(a[2]), "r"(a[3]), "r"(b0), "r"(b1));
}
__device__ __forceinline__ void cp16(uint32_t s, const void* g) {
    asm volatile("cp.async.cg.shared.global [%0], [%1], 16;" :: "r"(s), "l"(g));
}
__device__ __forceinline__ void cp_commit() {
    asm volatile("cp.async.commit_group;" ::: "memory");
}
__device__ __forceinline__ void cp_wait0() {
    asm volatile("cp.async.wait_group 0;" ::: "memory");
}
__device__ __forceinline__ uint32_t fkey(float v) {
    uint32_t b = __float_as_uint(v);
    return (b & 0x80000000u) ? ~b : (b | 0x80000000u);
}

// ---------------- prep: norms + s8 pack + per-launch state reset ----------------
// grid 128: blk = tile*8 + sub. sub owns nt = sub*2 + {0,1} + 16 cnorm rows.
// Also resets g_tokmin (one elem per thread), g_pair, g_done.
__global__ void __launch_bounds__(256) vq_prep(const float* __restrict__ cb) {
    __shared__ float scn[16];
    int blk = blockIdx.x;
    int tile = blk >> 3;
    int sub = blk & 7;
    int tid = threadIdx.x;

    g_tokmin[blk * 256 + tid] = ~0ull;
    if (blk == 0 && tid < NPAIRS) g_pair[tid] = 0u;
    if (blk == 0 && tid == 0) g_done = 0u;

    if (tid < 16) {
        int k = tile * 128 + sub * 16 + tid;
        const float* r = cb + (size_t)k * DIM;
        float s = 0.f;
#pragma unroll
        for (int c4 = 0; c4 < DIM / 4; ++c4) {
            float4 v = *(const float4*)(r + c4 * 4);
            s += v.x * v.x + v.y * v.y + v.z * v.z + v.w * v.w;
        }
        g_cnorm[k] = s;
        scn[tid] = s;
    }
    __syncthreads();
    if (tid < 16) {
        int tig = tid >> 2, r = tid & 3;
        int local = (r >> 1) * 8 + tig * 2 + (r & 1);   // code within sub's 16
        g_cni[tile * 128 + sub * 16 + tid] = __float2int_rn(-scn[local] * INV2S2);
    }

    if (tid < 64) {
        int nt = sub * 2 + (tid >> 5);
        int lane = tid & 31;
        int code = tile * 128 + nt * 8 + (lane >> 2);
        int kb = (lane & 3) * 4;
        const float* row = cb + (size_t)code * DIM;
        uint32_t* dst = g_cbq + (size_t)tile * 2048 + nt * 128 + lane * 4;
        dst[0] = pack4(row[kb + 0],  row[kb + 1],  row[kb + 2],  row[kb + 3]);
        dst[1] = pack4(row[kb + 16], row[kb + 17], row[kb + 18], row[kb + 19]);
        dst[2] = pack4(row[kb + 32], row[kb + 33], row[kb + 34], row[kb + 35]);
        dst[3] = pack4(row[kb + 48], row[kb + 49], row[kb + 50], row[kb + 51]);
    }
}

// ---------------- main kernel: code-split halves, fused epilogue+finalize ----------------
__global__ void __launch_bounds__(NTHREADS, 3)
vq_main(const float* __restrict__ lat, const float* __restrict__ tgt,
        const float* __restrict__ cb, const float* __restrict__ dw,
        const float* __restrict__ db, float* __restrict__ out, int out_size) {
    extern __shared__ char sm[];
    float* As = (float*)(sm + A_OFF);
    const uint32_t smem_base = smem_u32(sm);
    uint32_t* scnt = (uint32_t*)(sm + CNT_OFF);
    const int tid = threadIdx.x;
    const int lane = tid & 31;
    const int w = tid >> 5;              // 0..7
    const int gid = lane >> 2;           // 0..7  token-row group
    const int tig = lane & 3;            // 0..3  col group
    const int pair = blockIdx.x >> 1;    // token tile 0..255
    const int half = blockIdx.x & 1;     // code half
    const int n = pair >> 3;             // image (8 pairs per image)
    const int hw0 = (pair & 7) * TOK_TILE;
    uint32_t* wl = (uint32_t*)(sm + LIST_OFF) + w * WLIST;
    unsigned long long* tokmin = g_tokmin + pair * TOK_TILE;

    if (tid < 192) ((float*)(sm + DW_OFF))[tid] = dw[tid];
    if (tid < 3)   ((float*)(sm + DB_OFF))[tid] = db[tid];
    if (tid < NWARPS) scnt[tid] = 0u;

    // ---- stage A (fp32) [k][token]: 64 k x 128 tokens ----
    const float* latbase = lat + (size_t)n * DIM * HW + hw0;
    {
        int tl = tid & 31;
        int cgrp = tid >> 5;
#pragma unroll
        for (int p = 0; p < 8; ++p) {
            int c = p * 8 + cgrp;
            float4 v = *(const float4*)(latbase + (size_t)c * HW + tl * 4);
            *(float4*)&As[c * A_STRIDE + tl * 4] = v;
        }
    }

    // ---- preload B tile (half's first) + cni ----
    const int g0 = half * HTILES;
    {
        const float4* src = (const float4*)(g_cbq + (size_t)g0 * 2048);
        uint32_t dst = smem_base + B_OFF;
#pragma unroll 2
        for (int idx = tid; idx < 512; idx += NTHREADS)
            cp16(dst + (uint32_t)idx * 16u, src + idx);
        if (tid < 32)
            cp16(smem_base + CN_OFF + (uint32_t)tid * 16u,
                 ((const float4*)(g_cni + g0 * 128)) + tid);
        cp_commit();
    }
    cp_wait0();
    __syncthreads();

    // ---- resident A s8 fragments (warp = 16 tokens x this half's codes) ----
    uint32_t aq[2][4];
    const int t0 = w * 16 + gid;
#pragma unroll
    for (int c = 0; c < 2; ++c) {
        int kb = c * 32 + tig * 4;
        aq[c][0] = pack4(As[(kb + 0) * A_STRIDE + t0], As[(kb + 1) * A_STRIDE + t0],
                         As[(kb + 2) * A_STRIDE + t0], As[(kb + 3) * A_STRIDE + t0]);
        aq[c][1] = pack4(As[(kb + 0) * A_STRIDE + t0 + 8], As[(kb + 1) * A_STRIDE + t0 + 8],
                         As[(kb + 2) * A_STRIDE + t0 + 8], As[(kb + 3) * A_STRIDE + t0 + 8]);
        aq[c][2] = pack4(As[(kb + 16) * A_STRIDE + t0], As[(kb + 17) * A_STRIDE + t0],
                         As[(kb + 18) * A_STRIDE + t0], As[(kb + 19) * A_STRIDE + t0]);
        aq[c][3] = pack4(As[(kb + 16) * A_STRIDE + t0 + 8], As[(kb + 17) * A_STRIDE + t0 + 8],
                         As[(kb + 18) * A_STRIDE + t0 + 8], As[(kb + 19) * A_STRIDE + t0 + 8]);
    }

    int maxd0 = -2000000000, maxd1 = -2000000000;

    // 9 iterations: half's tiles 0..7, then tile 0 again (appends from i=1)
    for (int i = 0; i <= HTILES; ++i) {
        int cur = i & 1;
        if (i < HTILES) {
            int nxt = (i + 1 == HTILES) ? g0 : g0 + i + 1;
            const float4* src = (const float4*)(g_cbq + (size_t)nxt * 2048);
            uint32_t dst = smem_base + B_OFF + (uint32_t)(cur ^ 1) * B_BUF;
#pragma unroll 2
            for (int idx = tid; idx < 512; idx += NTHREADS)
                cp16(dst + (uint32_t)idx * 16u, src + idx);
            if (tid < 32)
                cp16(smem_base + CN_OFF + (uint32_t)(cur ^ 1) * 512u + (uint32_t)tid * 16u,
                     ((const float4*)(g_cni + nxt * 128)) + tid);
            cp_commit();
        }

        const char* smB = sm + B_OFF + (uint32_t)cur * B_BUF;
        const int4* cni4 = (const int4*)(sm + CN_OFF + (uint32_t)cur * 512u);
        const int gi = (i == HTILES) ? g0 : g0 + i;
        const int cbase = gi * 128;
        const bool appending = (i > 0);
        const uint4* bp = (const uint4*)smB;

#pragma unroll
        for (int ntp = 0; ntp < 8; ++ntp) {
            int nt0 = ntp * 2;
            uint4 b0 = bp[nt0 * 32 + lane];
            uint4 b1 = bp[(nt0 + 1) * 32 + lane];
            int4 cn4 = cni4[ntp * 4 + tig];

            int dA[4] = {cn4.x, cn4.y, cn4.x, cn4.y};
            int dB[4] = {cn4.z, cn4.w, cn4.z, cn4.w};
            mma_s8(dA, aq[0], b0.x, b0.y);
            mma_s8(dB, aq[0], b1.x, b1.y);
            mma_s8(dA, aq[1], b0.z, b0.w);
            mma_s8(dB, aq[1], b1.z, b1.w);

            int r0 = max(max(dA[0], dA[1]), max(dB[0], dB[1]));
            int r1 = max(max(dA[2], dA[3]), max(dB[2], dB[3]));
            bool pass = (r0 > maxd0 - M_INT) | (r1 > maxd1 - M_INT);
            if (appending) {
                if (__any_sync(0xFFFFFFFFu, pass)) {
                    int lim0 = maxd0 - M_INT, lim1 = maxd1 - M_INT;
                    int cA = cbase + nt0 * 8 + tig * 2;
                    int cB = cA + 8;
                    if (dA[0] > lim0) { uint32_t p = atomicAdd(&scnt[w], 1u); if (p < WLIST) wl[p] = ((uint32_t)t0 << 11) | (uint32_t)cA; }
                    if (dA[1] > lim0) { uint32_t p = atomicAdd(&scnt[w], 1u); if (p < WLIST) wl[p] = ((uint32_t)t0 << 11) | (uint32_t)(cA + 1); }
                    if (dA[2] > lim1) { uint32_t p = atomicAdd(&scnt[w], 1u); if (p < WLIST) wl[p] = ((uint32_t)(t0 + 8) << 11) | (uint32_t)cA; }
                    if (dA[3] > lim1) { uint32_t p = atomicAdd(&scnt[w], 1u); if (p < WLIST) wl[p] = ((uint32_t)(t0 + 8) << 11) | (uint32_t)(cA + 1); }
                    if (dB[0] > lim0) { uint32_t p = atomicAdd(&scnt[w], 1u); if (p < WLIST) wl[p] = ((uint32_t)t0 << 11) | (uint32_t)cB; }
                    if (dB[1] > lim0) { uint32_t p = atomicAdd(&scnt[w], 1u); if (p < WLIST) wl[p] = ((uint32_t)t0 << 11) | (uint32_t)(cB + 1); }
                    if (dB[2] > lim1) { uint32_t p = atomicAdd(&scnt[w], 1u); if (p < WLIST) wl[p] = ((uint32_t)(t0 + 8) << 11) | (uint32_t)cB; }
                    if (dB[3] > lim1) { uint32_t p = atomicAdd(&scnt[w], 1u); if (p < WLIST) wl[p] = ((uint32_t)(t0 + 8) << 11) | (uint32_t)(cB + 1); }
                }
            }
            maxd0 = max(maxd0, r0);
            maxd1 = max(maxd1, r1);
        }
        maxd0 = max(maxd0, __shfl_xor_sync(0xFFFFFFFFu, maxd0, 1));
        maxd0 = max(maxd0, __shfl_xor_sync(0xFFFFFFFFu, maxd0, 2));
        maxd1 = max(maxd1, __shfl_xor_sync(0xFFFFFFFFu, maxd1, 1));
        maxd1 = max(maxd1, __shfl_xor_sync(0xFFFFFFFFu, maxd1, 2));

        cp_wait0();
        __syncthreads();
    }

    // ---- exact fp32 refinement -> GLOBAL per-token argmin ----
    {
        uint32_t mycnt = scnt[w];
        if (mycnt > WLIST) mycnt = WLIST;
        for (uint32_t idx = lane; idx < mycnt; idx += 32) {
            uint32_t e = wl[idx];
            int t = (int)(e >> 11);
            int c = (int)(e & 2047u);
            const float4* er = (const float4*)(cb + (size_t)c * DIM);
            float dot = 0.f;
#pragma unroll
            for (int k4 = 0; k4 < 16; ++k4) {
                float4 ev = er[k4];
                dot += ev.x * As[(k4 * 4 + 0) * A_STRIDE + t]
                     + ev.y * As[(k4 * 4 + 1) * A_STRIDE + t]
                     + ev.z * As[(k4 * 4 + 2) * A_STRIDE + t]
                     + ev.w * As[(k4 * 4 + 3) * A_STRIDE + t];
            }
            float val = g_cnorm[c] - 2.0f * dot;
            unsigned long long pk = ((unsigned long long)fkey(val) << 32) | (unsigned)c;
            atomicMin(&tokmin[t], pk);
        }
    }
    __syncthreads();

    // ---- pair rendezvous: second block of the pair runs the epilogue ----
    __shared__ bool s_second;
    __threadfence();
    if (tid == 0) {
        unsigned v = atomicAdd(&g_pair[pair], 1u);
        s_second = (v == 1u);
    }
    __syncthreads();
    if (!s_second) return;
    __threadfence();   // make partner's tokmin writes visible

    // ---- exact fp32 epilogue ----
    float my_vq = 0.f, my_rc = 0.f;
    if (tid < TOK_TILE) {
        int bi = (int)(tokmin[tid] & 0xFFFFFFFFu);
        const float* q = cb + (size_t)bi * DIM;
        const float* dws = (const float*)(sm + DW_OFF);
        const float* dbs = (const float*)(sm + DB_OFF);
        float y0 = dbs[0], y1 = dbs[1], y2 = dbs[2];
        float vq = 0.f;
#pragma unroll
        for (int c4 = 0; c4 < DIM / 4; ++c4) {
            float4 qv = *(const float4*)(q + c4 * 4);
            float qa[4] = {qv.x, qv.y, qv.z, qv.w};
#pragma unroll
            for (int r = 0; r < 4; ++r) {
                int c = c4 * 4 + r;
                float xc = As[c * A_STRIDE + tid];
                float dd = xc - qa[r];
                vq += dd * dd;
                y0 += dws[c] * qa[r];
                y1 += dws[DIM + c] * qa[r];
                y2 += dws[2 * DIM + c] * qa[r];
            }
        }
        const float* tg = tgt + (size_t)n * 3 * HW + hw0 + tid;
        float e0 = y0 - tg[0];
        float e1 = y1 - tg[HW];
        float e2 = y2 - tg[2 * HW];
        my_vq = vq;
        my_rc = e0 * e0 + e1 * e1 + e2 * e2;
    }
    __syncthreads();
    float* sv = (float*)(sm + RED_OFF);
    float* sr = sv + NTHREADS;
    sv[tid] = my_vq;
    sr[tid] = my_rc;
    __syncthreads();
    for (int s = NTHREADS / 2; s > 0; s >>= 1) {
        if (tid < s) { sv[tid] += sv[tid + s]; sr[tid] += sr[tid + s]; }
        __syncthreads();
    }
    if (tid == 0) {
        g_partial[pair] = sv[0];
        g_partial[NPAIRS + pair] = sr[0];
    }

    // ---- last-pair finalize (deterministic) ----
    __shared__ bool s_last;
    __threadfence();
    if (tid == 0) {
        unsigned v = atomicAdd(&g_done, 1u);
        s_last = (v == NPAIRS - 1);
    }
    __syncthreads();
    if (s_last) {
        float v = g_partial[tid];
        float r = g_partial[NPAIRS + tid];
        __syncthreads();
        sv[tid] = v;
        sr[tid] = r;
        __syncthreads();
        for (int s = NTHREADS / 2; s > 0; s >>= 1) {
            if (tid < s) { sv[tid] += sv[tid + s]; sr[tid] += sr[tid + s]; }
            __syncthreads();
        }
        for (int idx = tid; idx < out_size; idx += NTHREADS)
            if (idx >= 3) out[idx] = 0.f;
        if (tid == 0) {
            float vq_loss = 2.0f * sv[0] / (float)(NB * DIM * HW);
            float recon = sr[0] / (float)(NB * 3 * HW);
            if (out_size > 0) out[0] = vq_loss + recon;
            if (out_size > 1) out[1] = vq_loss;
            if (out_size > 2) out[2] = recon;
            g_done = 0;   // reset for next launch/replay
        }
    }
}

extern "C" void kernel_launch(void* const* d_in, const int* in_sizes, int n_in,
                              void* d_out, int out_size) {
    const float* lat = (const float*)d_in[0];
    const float* tgt = (const float*)d_in[1];
    const float* cb  = (const float*)d_in[2];
    const float* dw  = (const float*)d_in[3];
    const float* db  = (const float*)d_in[4];
    float* out = (float*)d_out;

    vq_prep<<<128, 256>>>(cb);

    cudaFuncSetAttribute(vq_main, cudaFuncAttributeMaxDynamicSharedMemorySize, SMEM_TOTAL);
    vq_main<<<NBLOCKS, NTHREADS, SMEM_TOTAL>>>(lat, tgt, cb, dw, db, out, out_size);
}